// round 9
// baseline (speedup 1.0000x reference)
#include <cuda_runtime.h>

#define CAR     8
#define NAG     64
#define HID     256
#define ENC     257
#define QIN     265
#define ADIM    30
#define SROW    520
#define M_ROWS  64
#define NPAD    264
#define KPAIRS  16
#define NTILES  33
#define HPITCH  272      // mod 32 == 16 -> conflict-free LDS.128 A-frag loads

// B layout: [pair][tile][lane]{b0_even,b1_even,b0_odd,b1_odd}
#define W2F_ELEMS (KPAIRS * NTILES * 32 * 4)   // 67584

__device__ __align__(16) float g_W2f[W2F_ELEMS];
__device__ float g_b2p[NPAD];
__device__ __align__(16) float g_x[8192 * 272];

// kernel1 shared (floats)
#define OFF_H   0
#define OFF_S   (OFF_H + M_ROWS * HPITCH)   // 17408
#define OFF_V   (OFF_S + SROW)              // 17928
#define OFF_X   (OFF_V + M_ROWS)            // 17992
#define OFF_B2  (OFF_X + 272)               // 18264
#define SM1_FLOATS (OFF_B2 + NPAD)          // 18528
#define SM1_BYTES  (SM1_FLOATS * 4)         // 74112

// kernel2 shared
#define SM2_BYTES ((64 * 272 + 64 * 256) * 4)  // 135168

__device__ __forceinline__ unsigned cvt_tf32(float x) {
    unsigned r; asm("cvt.rna.tf32.f32 %0, %1;" : "=r"(r) : "f"(x)); return r;
}
__device__ __forceinline__ void mma_tf32(float* c, const unsigned* a,
                                         unsigned b0, unsigned b1) {
    asm("mma.sync.aligned.m16n8k8.row.col.f32.tf32.tf32.f32 "
        "{%0,%1,%2,%3},{%4,%5,%6,%7},{%8,%9},{%0,%1,%2,%3};"
        : "+f"(c[0]), "+f"(c[1]), "+f"(c[2]), "+f"(c[3])
        : "r"(a[0]), "r"(a[1]), "r"(a[2]), "r"(a[3]), "r"(b0), "r"(b1));
}

// pack W2 tf32-rna into paired-k fragment layout (mapping validated in R6/R7)
__global__ void prepack(const float* __restrict__ W2, const float* __restrict__ b2) {
    int idx = blockIdx.x * 256 + threadIdx.x;
    if (idx < W2F_ELEMS) {
        int q    = idx & 3;
        int rem  = idx >> 2;
        int lane = rem & 31;
        int rem2 = rem >> 5;
        int t    = rem2 % NTILES;
        int p    = rem2 / NTILES;
        int e    = t * 8 + (lane >> 2);
        int k    = (2 * p + (q >> 1)) * 8 + (lane & 3) + (q & 1) * 4;
        float v  = (e < ENC) ? W2[k * ENC + e] : 0.0f;
        g_W2f[idx] = __uint_as_float(cvt_tf32(v));
    }
    if (idx < NPAD) g_b2p[idx] = (idx < ENC) ? b2[idx] : 0.0f;
}

// ================= kernel 1: encoder (phases 0-3) -> g_x =================
__global__ void __launch_bounds__(256, 3) enc_kernel(
    const float* __restrict__ s,
    const float* __restrict__ W1, const float* __restrict__ b1)
{
    extern __shared__ float sm[];
    float* h_sh  = sm + OFF_H;
    float* s_sh  = sm + OFF_S;
    float* v_sh  = sm + OFF_V;
    float* x_sh  = sm + OFF_X;
    float* b2_sh = sm + OFF_B2;

    const int tid  = threadIdx.x;
    const int lane = tid & 31;
    const int wid  = tid >> 5;
    const int bid  = blockIdx.x;

    // ---- stage s row, zero x, stage b2 ----
    {
        const float4* srow4 = reinterpret_cast<const float4*>(s + (size_t)bid * SROW);
        float4* ssh4 = reinterpret_cast<float4*>(s_sh);
        if (tid < SROW / 4) ssh4[tid] = srow4[tid];
        for (int i = tid; i < 272; i += 256) x_sh[i] = 0.0f;
        for (int i = tid; i < NPAD; i += 256) b2_sh[i] = g_b2p[i];
    }
    __syncthreads();

    if (tid < NAG) {        // validity: exact fp32 compare
        bool v = true;
        #pragma unroll
        for (int c = 0; c < CAR; c++)
            v = v && (s_sh[CAR + tid * CAR + c] != -1.0f);
        v_sh[tid] = v ? 1.0f : 0.0f;
    }

    // ---- phase 1: h (tf32), 16-group k-permutation: pos = 4*(k&3) + ((k>>2)&3) ----
    {
        const int k = tid;
        float w1r[CAR];
        #pragma unroll
        for (int c = 0; c < CAR; c++) w1r[c] = W1[c * HID + k];
        const float bk = b1[k];
        const int pos = (k & ~15) + 4 * (k & 3) + ((k >> 2) & 3);
        #pragma unroll 4
        for (int m = 0; m < M_ROWS; m++) {
            const float* sp = s_sh + CAR + m * CAR;
            float a = bk;
            #pragma unroll
            for (int c = 0; c < CAR; c++) a = fmaf(sp[c], w1r[c], a);
            h_sh[m * HPITCH + pos] = __uint_as_float(cvt_tf32(fmaxf(a, 0.0f)));
        }
    }
    if (tid < CAR) x_sh[tid] = s_sh[tid];   // self states
    __syncthreads();
    // ============ no __syncthreads inside the GEMM mainloop ============

    // ---- phase 2: tf32 mma, M=64 x N=264 x K=256; 8 warps = 2 mw x 4 ns ----
    // N-tiles chunked 3-at-a-time so acc stays small and B is double-buffered.
    const int mw = wid & 1;
    const int ns = wid >> 1;
    const int ntiles = ns ? 8 : 9;
    const int tbase  = ns ? (1 + ns * 8) : 0;

    const float* habase = h_sh + (mw * 32 + (lane >> 2)) * HPITCH + (lane & 3) * 4;
    const float4* bgl4  = reinterpret_cast<const float4*>(g_W2f) + lane;

    const int mrow = mw * 32 + (lane >> 2);
    const float va = v_sh[mrow],      vb = v_sh[mrow + 8];
    const float vc = v_sh[mrow + 16], vd = v_sh[mrow + 24];

    for (int ch = 0; ch < 3; ch++) {
        const int ct0 = ch * 3;
        const int cnt = (ntiles - ct0 < 3) ? (ntiles - ct0) : 3;   // 3 or 2

        float acc[2][3][4];
        #pragma unroll
        for (int t = 0; t < 3; t++) {
            if (t < cnt) {
                const int e0 = (tbase + ct0 + t) * 8 + (lane & 3) * 2;
                const float bb0 = b2_sh[e0], bb1 = b2_sh[e0 + 1];
                #pragma unroll
                for (int mt = 0; mt < 2; mt++) {
                    acc[mt][t][0] = bb0; acc[mt][t][1] = bb1;
                    acc[mt][t][2] = bb0; acc[mt][t][3] = bb1;
                }
            }
        }

        float4 bc[3], bn[3];
        #pragma unroll
        for (int t = 0; t < 3; t++)
            if (t < cnt) bc[t] = bgl4[(tbase + ct0 + t) * 32];

        for (int p = 0; p < KPAIRS; p++) {
            if (p + 1 < KPAIRS) {       // prefetch next pair's B
                #pragma unroll
                for (int t = 0; t < 3; t++)
                    if (t < cnt)
                        bn[t] = bgl4[((p + 1) * NTILES + tbase + ct0 + t) * 32];
            }
            // A fragments: 2 LDS.128 per mt (rows r and r+8), 16 k-values
            unsigned ae[2][4], ao[2][4];
            #pragma unroll
            for (int mt = 0; mt < 2; mt++) {
                const float* hp = habase + mt * 16 * HPITCH + p * 16;
                float4 lo = *reinterpret_cast<const float4*>(hp);
                float4 hi = *reinterpret_cast<const float4*>(hp + 8 * HPITCH);
                ae[mt][0] = __float_as_uint(lo.x); ae[mt][1] = __float_as_uint(hi.x);
                ae[mt][2] = __float_as_uint(lo.y); ae[mt][3] = __float_as_uint(hi.y);
                ao[mt][0] = __float_as_uint(lo.z); ao[mt][1] = __float_as_uint(hi.z);
                ao[mt][2] = __float_as_uint(lo.w); ao[mt][3] = __float_as_uint(hi.w);
            }
            #pragma unroll
            for (int t = 0; t < 3; t++) {
                if (t < cnt) {
                    const unsigned b0  = __float_as_uint(bc[t].x);
                    const unsigned b1  = __float_as_uint(bc[t].y);
                    const unsigned b2v = __float_as_uint(bc[t].z);
                    const unsigned b3  = __float_as_uint(bc[t].w);
                    mma_tf32(acc[0][t], ae[0], b0, b1);
                    mma_tf32(acc[1][t], ae[1], b0, b1);
                    mma_tf32(acc[0][t], ao[0], b2v, b3);
                    mma_tf32(acc[1][t], ao[1], b2v, b3);
                }
            }
            #pragma unroll
            for (int t = 0; t < 3; t++)
                if (t < cnt) bc[t] = bn[t];
        }

        // chunk epilogue: relu * valid, reduce rows, accumulate into x
        #pragma unroll
        for (int t = 0; t < 3; t++) {
            if (t < cnt) {
                float se = fmaxf(acc[0][t][0], 0.0f) * va + fmaxf(acc[0][t][2], 0.0f) * vb
                         + fmaxf(acc[1][t][0], 0.0f) * vc + fmaxf(acc[1][t][2], 0.0f) * vd;
                float so = fmaxf(acc[0][t][1], 0.0f) * va + fmaxf(acc[0][t][3], 0.0f) * vb
                         + fmaxf(acc[1][t][1], 0.0f) * vc + fmaxf(acc[1][t][3], 0.0f) * vd;
                #pragma unroll
                for (int off = 4; off < 32; off <<= 1) {
                    se += __shfl_xor_sync(0xffffffffu, se, off);
                    so += __shfl_xor_sync(0xffffffffu, so, off);
                }
                if (lane < 4) {
                    const int e = (tbase + ct0 + t) * 8 + lane * 2;
                    atomicAdd(&x_sh[8 + e], se);
                    atomicAdd(&x_sh[9 + e], so);
                }
            }
        }
    }
    __syncthreads();

    for (int i = tid; i < 272; i += 256) g_x[(size_t)bid * 272 + i] = x_sh[i];
}

// ================= kernel 2: Q-head, 64 rows per CTA =================
__global__ void __launch_bounds__(256, 1) qhead_kernel(
    const float* __restrict__ Qw1, const float* __restrict__ Qb1,
    const float* __restrict__ Qw2, const float* __restrict__ Qb2,
    float* __restrict__ out)
{
    extern __shared__ float sm[];
    float* x_sh = sm;                  // 64 x 272
    float* y_sh = sm + 64 * 272;       // 64 x 256

    const int tid = threadIdx.x;
    const int bid = blockIdx.x;

    {   // stage 64 x-rows
        const float4* src = reinterpret_cast<const float4*>(g_x + (size_t)bid * 64 * 272);
        float4* dst = reinterpret_cast<float4*>(x_sh);
        for (int i = tid; i < 64 * 272 / 4; i += 256) dst[i] = src[i];
    }
    __syncthreads();

    // y = relu(x @ Qw1 + Qb1): 4 passes of 16 rows, thread owns column j
    const int j = tid;
    const float bj = Qb1[j];
    for (int pass = 0; pass < 4; pass++) {
        const int rbase = pass * 16;
        float acc[16];
        #pragma unroll
        for (int rr = 0; rr < 16; rr++) acc[rr] = bj;
        for (int i = 0; i < QIN; i++) {
            const float w = Qw1[i * HID + j];
            const float* xp = x_sh + rbase * 272 + i;
            #pragma unroll
            for (int rr = 0; rr < 16; rr++)
                acc[rr] = fmaf(xp[rr * 272], w, acc[rr]);
        }
        #pragma unroll
        for (int rr = 0; rr < 16; rr++)
            y_sh[(rbase + rr) * 256 + j] = fmaxf(acc[rr], 0.0f);
    }
    __syncthreads();

    // q = y @ Qw2 + Qb2
    for (int idx = tid; idx < 64 * ADIM; idx += 256) {
        const int r = idx / ADIM, aq = idx % ADIM;
        float q = Qb2[aq];
        const float* yy = y_sh + r * 256;
        #pragma unroll 8
        for (int k = 0; k < HID; k++)
            q = fmaf(yy[k], Qw2[k * ADIM + aq], q);
        out[((size_t)bid * 64 + r) * ADIM + aq] = q;
    }
}

extern "C" void kernel_launch(void* const* d_in, const int* in_sizes, int n_in,
                              void* d_out, int out_size) {
    const float* s   = (const float*)d_in[0];
    const float* W1  = (const float*)d_in[1];
    const float* b1  = (const float*)d_in[2];
    const float* W2  = (const float*)d_in[3];
    const float* b2  = (const float*)d_in[4];
    const float* Qw1 = (const float*)d_in[5];
    const float* Qb1 = (const float*)d_in[6];
    const float* Qw2 = (const float*)d_in[7];
    const float* Qb2 = (const float*)d_in[8];
    float* out = (float*)d_out;

    prepack<<<(W2F_ELEMS + 255) / 256, 256>>>(W2, b2);

    cudaFuncSetAttribute(enc_kernel,
                         cudaFuncAttributeMaxDynamicSharedMemorySize, SM1_BYTES);
    enc_kernel<<<8192, 256, SM1_BYTES>>>(s, W1, b1);

    cudaFuncSetAttribute(qhead_kernel,
                         cudaFuncAttributeMaxDynamicSharedMemorySize, SM2_BYTES);
    qhead_kernel<<<128, 256, SM2_BYTES>>>(Qw1, Qb1, Qw2, Qb2, out);
}

// round 10
// speedup vs baseline: 1.3158x; 1.3158x over previous
#include <cuda_runtime.h>

#define CAR     8
#define NAG     64
#define HID     256
#define ENC     257
#define QIN     265
#define ADIM    30
#define SROW    520
#define M_ROWS  64
#define NPAD    264
#define KPAIRS  16
#define NTILES  33
#define HPITCH  272      // mod 32 == 16 -> conflict-free LDS.128 A-frag loads

// B layout: [pair][tile][lane]{b0_even,b1_even,b0_odd,b1_odd}
#define W2F_ELEMS (KPAIRS * NTILES * 32 * 4)   // 67584

__device__ __align__(16) float g_W2f[W2F_ELEMS];
__device__ float g_b2p[NPAD];
__device__ __align__(16) float g_x[8192 * 272];

// kernel1 shared (floats)
#define OFF_H   0
#define OFF_S   (OFF_H + M_ROWS * HPITCH)   // 17408
#define OFF_V   (OFF_S + SROW)              // 17928
#define OFF_X   (OFF_V + M_ROWS)            // 17992
#define OFF_B2  (OFF_X + 272)               // 18264
#define SM1_FLOATS (OFF_B2 + NPAD)          // 18528
#define SM1_BYTES  (SM1_FLOATS * 4)         // 74112

// kernel2 shared
#define SM2_BYTES ((64 * 272 + 64 * 256) * 4)  // 135168

__device__ __forceinline__ unsigned cvt_tf32(float x) {
    unsigned r; asm("cvt.rna.tf32.f32 %0, %1;" : "=r"(r) : "f"(x)); return r;
}
__device__ __forceinline__ void mma_tf32(float* c, const unsigned* a,
                                         unsigned b0, unsigned b1) {
    asm("mma.sync.aligned.m16n8k8.row.col.f32.tf32.tf32.f32 "
        "{%0,%1,%2,%3},{%4,%5,%6,%7},{%8,%9},{%0,%1,%2,%3};"
        : "+f"(c[0]), "+f"(c[1]), "+f"(c[2]), "+f"(c[3])
        : "r"(a[0]), "r"(a[1]), "r"(a[2]), "r"(a[3]), "r"(b0), "r"(b1));
}

// pack W2 tf32-rna into paired-k fragment layout (mapping validated R6-R8)
__global__ void prepack(const float* __restrict__ W2, const float* __restrict__ b2) {
    int idx = blockIdx.x * 256 + threadIdx.x;
    if (idx < W2F_ELEMS) {
        int q    = idx & 3;
        int rem  = idx >> 2;
        int lane = rem & 31;
        int rem2 = rem >> 5;
        int t    = rem2 % NTILES;
        int p    = rem2 / NTILES;
        int e    = t * 8 + (lane >> 2);
        int k    = (2 * p + (q >> 1)) * 8 + (lane & 3) + (q & 1) * 4;
        float v  = (e < ENC) ? W2[k * ENC + e] : 0.0f;
        g_W2f[idx] = __uint_as_float(cvt_tf32(v));
    }
    if (idx < NPAD) g_b2p[idx] = (idx < ENC) ? b2[idx] : 0.0f;
}

// ================= kernel 1: encoder (phases 0-3) -> g_x =================
__global__ void __launch_bounds__(256, 2) enc_kernel(
    const float* __restrict__ s,
    const float* __restrict__ W1, const float* __restrict__ b1)
{
    extern __shared__ float sm[];
    float* h_sh  = sm + OFF_H;
    float* s_sh  = sm + OFF_S;
    float* v_sh  = sm + OFF_V;
    float* x_sh  = sm + OFF_X;
    float* b2_sh = sm + OFF_B2;

    const int tid  = threadIdx.x;
    const int lane = tid & 31;
    const int wid  = tid >> 5;
    const int bid  = blockIdx.x;

    // ---- stage s row, zero x, stage b2 ----
    {
        const float4* srow4 = reinterpret_cast<const float4*>(s + (size_t)bid * SROW);
        float4* ssh4 = reinterpret_cast<float4*>(s_sh);
        if (tid < SROW / 4) ssh4[tid] = srow4[tid];
        for (int i = tid; i < 272; i += 256) x_sh[i] = 0.0f;
        for (int i = tid; i < NPAD; i += 256) b2_sh[i] = g_b2p[i];
    }
    __syncthreads();

    if (tid < NAG) {        // validity: exact fp32 compare
        bool v = true;
        #pragma unroll
        for (int c = 0; c < CAR; c++)
            v = v && (s_sh[CAR + tid * CAR + c] != -1.0f);
        v_sh[tid] = v ? 1.0f : 0.0f;
    }

    // ---- phase 1: h (tf32), 16-group k-permutation: pos = 4*(k&3) + ((k>>2)&3) ----
    {
        const int k = tid;
        float w1r[CAR];
        #pragma unroll
        for (int c = 0; c < CAR; c++) w1r[c] = W1[c * HID + k];
        const float bk = b1[k];
        const int pos = (k & ~15) + 4 * (k & 3) + ((k >> 2) & 3);
        #pragma unroll 4
        for (int m = 0; m < M_ROWS; m++) {
            const float* sp = s_sh + CAR + m * CAR;
            float a = bk;
            #pragma unroll
            for (int c = 0; c < CAR; c++) a = fmaf(sp[c], w1r[c], a);
            h_sh[m * HPITCH + pos] = __uint_as_float(cvt_tf32(fmaxf(a, 0.0f)));
        }
    }
    if (tid < CAR) x_sh[tid] = s_sh[tid];   // self states
    __syncthreads();
    // ============ no __syncthreads inside the GEMM mainloop ============

    // ---- phase 2: tf32 mma, M=64 x N=264 x K=256; 8 warps = 2 mw x 4 ns ----
    // N-tiles in 2 chunks (5+4 / 4+4): acc stays 40 regs, B fully pair-ahead
    // register double-buffered (bc[5]+bn[5]) under the 128-reg occ-2 cap.
    const int mw = wid & 1;
    const int ns = wid >> 1;
    const int ntiles = ns ? 8 : 9;
    const int tbase  = ns ? (1 + ns * 8) : 0;
    const int c0     = ns ? 4 : 5;        // first-chunk size

    const float* habase = h_sh + (mw * 32 + (lane >> 2)) * HPITCH + (lane & 3) * 4;
    const float4* bgl4  = reinterpret_cast<const float4*>(g_W2f) + lane;

    const int mrow = mw * 32 + (lane >> 2);
    const float va = v_sh[mrow],      vb = v_sh[mrow + 8];
    const float vc = v_sh[mrow + 16], vd = v_sh[mrow + 24];

    for (int ch = 0; ch < 2; ch++) {
        const int ct0 = ch ? c0 : 0;
        const int cnt = ch ? (ntiles - c0) : c0;   // 5/4 or 4/4

        float acc[2][5][4];
        #pragma unroll
        for (int t = 0; t < 5; t++) {
            if (t < cnt) {
                const int e0 = (tbase + ct0 + t) * 8 + (lane & 3) * 2;
                const float bb0 = b2_sh[e0], bb1 = b2_sh[e0 + 1];
                #pragma unroll
                for (int mt = 0; mt < 2; mt++) {
                    acc[mt][t][0] = bb0; acc[mt][t][1] = bb1;
                    acc[mt][t][2] = bb0; acc[mt][t][3] = bb1;
                }
            }
        }

        float4 bc[5], bn[5];
        #pragma unroll
        for (int t = 0; t < 5; t++)
            if (t < cnt) bc[t] = bgl4[(tbase + ct0 + t) * 32];

        for (int p = 0; p < KPAIRS; p++) {
            if (p + 1 < KPAIRS) {       // prefetch next pair's B (full lookahead)
                #pragma unroll
                for (int t = 0; t < 5; t++)
                    if (t < cnt)
                        bn[t] = bgl4[((p + 1) * NTILES + tbase + ct0 + t) * 32];
            }
            // A fragments: 2 LDS.128 per mt (rows r and r+8), 16 k-values
            unsigned ae[2][4], ao[2][4];
            #pragma unroll
            for (int mt = 0; mt < 2; mt++) {
                const float* hp = habase + mt * 16 * HPITCH + p * 16;
                float4 lo = *reinterpret_cast<const float4*>(hp);
                float4 hi = *reinterpret_cast<const float4*>(hp + 8 * HPITCH);
                ae[mt][0] = __float_as_uint(lo.x); ae[mt][1] = __float_as_uint(hi.x);
                ae[mt][2] = __float_as_uint(lo.y); ae[mt][3] = __float_as_uint(hi.y);
                ao[mt][0] = __float_as_uint(lo.z); ao[mt][1] = __float_as_uint(hi.z);
                ao[mt][2] = __float_as_uint(lo.w); ao[mt][3] = __float_as_uint(hi.w);
            }
            #pragma unroll
            for (int t = 0; t < 5; t++) {
                if (t < cnt) {
                    const unsigned b0  = __float_as_uint(bc[t].x);
                    const unsigned b1  = __float_as_uint(bc[t].y);
                    const unsigned b2v = __float_as_uint(bc[t].z);
                    const unsigned b3  = __float_as_uint(bc[t].w);
                    mma_tf32(acc[0][t], ae[0], b0, b1);
                    mma_tf32(acc[1][t], ae[1], b0, b1);
                    mma_tf32(acc[0][t], ao[0], b2v, b3);
                    mma_tf32(acc[1][t], ao[1], b2v, b3);
                }
            }
            #pragma unroll
            for (int t = 0; t < 5; t++)
                if (t < cnt) bc[t] = bn[t];
        }

        // chunk epilogue: relu * valid, reduce rows, accumulate into x
        #pragma unroll
        for (int t = 0; t < 5; t++) {
            if (t < cnt) {
                float se = fmaxf(acc[0][t][0], 0.0f) * va + fmaxf(acc[0][t][2], 0.0f) * vb
                         + fmaxf(acc[1][t][0], 0.0f) * vc + fmaxf(acc[1][t][2], 0.0f) * vd;
                float so = fmaxf(acc[0][t][1], 0.0f) * va + fmaxf(acc[0][t][3], 0.0f) * vb
                         + fmaxf(acc[1][t][1], 0.0f) * vc + fmaxf(acc[1][t][3], 0.0f) * vd;
                #pragma unroll
                for (int off = 4; off < 32; off <<= 1) {
                    se += __shfl_xor_sync(0xffffffffu, se, off);
                    so += __shfl_xor_sync(0xffffffffu, so, off);
                }
                if (lane < 4) {
                    const int e = (tbase + ct0 + t) * 8 + lane * 2;
                    atomicAdd(&x_sh[8 + e], se);
                    atomicAdd(&x_sh[9 + e], so);
                }
            }
        }
    }
    __syncthreads();

    for (int i = tid; i < 272; i += 256) g_x[(size_t)bid * 272 + i] = x_sh[i];
}

// ================= kernel 2: Q-head, 64 rows per CTA =================
__global__ void __launch_bounds__(256, 1) qhead_kernel(
    const float* __restrict__ Qw1, const float* __restrict__ Qb1,
    const float* __restrict__ Qw2, const float* __restrict__ Qb2,
    float* __restrict__ out)
{
    extern __shared__ float sm[];
    float* x_sh = sm;                  // 64 x 272
    float* y_sh = sm + 64 * 272;       // 64 x 256

    const int tid = threadIdx.x;
    const int bid = blockIdx.x;

    {   // stage 64 x-rows
        const float4* src = reinterpret_cast<const float4*>(g_x + (size_t)bid * 64 * 272);
        float4* dst = reinterpret_cast<float4*>(x_sh);
        for (int i = tid; i < 64 * 272 / 4; i += 256) dst[i] = src[i];
    }
    __syncthreads();

    // y = relu(x @ Qw1 + Qb1): 4 passes of 16 rows, thread owns column j
    const int j = tid;
    const float bj = Qb1[j];
    for (int pass = 0; pass < 4; pass++) {
        const int rbase = pass * 16;
        float acc[16];
        #pragma unroll
        for (int rr = 0; rr < 16; rr++) acc[rr] = bj;
        for (int i = 0; i < QIN; i++) {
            const float w = Qw1[i * HID + j];
            const float* xp = x_sh + rbase * 272 + i;
            #pragma unroll
            for (int rr = 0; rr < 16; rr++)
                acc[rr] = fmaf(xp[rr * 272], w, acc[rr]);
        }
        #pragma unroll
        for (int rr = 0; rr < 16; rr++)
            y_sh[(rbase + rr) * 256 + j] = fmaxf(acc[rr], 0.0f);
    }
    __syncthreads();

    // q = y @ Qw2 + Qb2
    for (int idx = tid; idx < 64 * ADIM; idx += 256) {
        const int r = idx / ADIM, aq = idx % ADIM;
        float q = Qb2[aq];
        const float* yy = y_sh + r * 256;
        #pragma unroll 8
        for (int k = 0; k < HID; k++)
            q = fmaf(yy[k], Qw2[k * ADIM + aq], q);
        out[((size_t)bid * 64 + r) * ADIM + aq] = q;
    }
}

extern "C" void kernel_launch(void* const* d_in, const int* in_sizes, int n_in,
                              void* d_out, int out_size) {
    const float* s   = (const float*)d_in[0];
    const float* W1  = (const float*)d_in[1];
    const float* b1  = (const float*)d_in[2];
    const float* W2  = (const float*)d_in[3];
    const float* b2  = (const float*)d_in[4];
    const float* Qw1 = (const float*)d_in[5];
    const float* Qb1 = (const float*)d_in[6];
    const float* Qw2 = (const float*)d_in[7];
    const float* Qb2 = (const float*)d_in[8];
    float* out = (float*)d_out;

    prepack<<<(W2F_ELEMS + 255) / 256, 256>>>(W2, b2);

    cudaFuncSetAttribute(enc_kernel,
                         cudaFuncAttributeMaxDynamicSharedMemorySize, SM1_BYTES);
    enc_kernel<<<8192, 256, SM1_BYTES>>>(s, W1, b1);

    cudaFuncSetAttribute(qhead_kernel,
                         cudaFuncAttributeMaxDynamicSharedMemorySize, SM2_BYTES);
    qhead_kernel<<<128, 256, SM2_BYTES>>>(Qw1, Qb1, Qw2, Qb2, out);
}